// round 9
// baseline (speedup 1.0000x reference)
#include <cuda_runtime.h>

#define FULL 0xffffffffu
#define L2E 1.4426950408889634f

typedef unsigned long long u64;

// shared layout offsets (floats), all lane-fastest (conflict-free)
#define L0W 0
#define L0B 256
#define L1Wa 512
#define L1Wb 640
#define L1B 768
#define L2Wa 896
#define L2Wb 960
#define L2B 1024
#define L3Wa 1088
#define L3Wb 1120
#define L3B 1152
#define L4W 1184
#define L4B 1216
#define L5W 1232
#define L5B 1248
#define L6W 1256
#define L6B 1264
#define L7W 1268
#define L7B 1272
#define L8W 1274
#define L8B 1276
#define SC  1280
#define SM_TOT 1288

struct TreeParams {
    const float* w[9];
    const float* b[9];
    const float* alpha;
    const float* beta;
    const float* gamma;
    const float* root_w;
    const float* root_b;
};

__device__ __forceinline__ float ex2f(float x) {
    float y; asm("ex2.approx.ftz.f32 %0, %1;" : "=f"(y) : "f"(x)); return y;
}
__device__ __forceinline__ float rcpf(float x) {
    float y; asm("rcp.approx.ftz.f32 %0, %1;" : "=f"(y) : "f"(x)); return y;
}

// ---- f32x2 packed helpers ----
__device__ __forceinline__ u64 pk(float lo, float hi) {
    u64 r; asm("mov.b64 %0, {%1, %2};" : "=l"(r) : "f"(lo), "f"(hi)); return r;
}
__device__ __forceinline__ void upk(u64 v, float& lo, float& hi) {
    asm("mov.b64 {%0, %1}, %2;" : "=f"(lo), "=f"(hi) : "l"(v));
}
__device__ __forceinline__ u64 fma2(u64 a, u64 b, u64 c) {
    u64 d; asm("fma.rn.f32x2 %0, %1, %2, %3;" : "=l"(d) : "l"(a), "l"(b), "l"(c)); return d;
}
__device__ __forceinline__ u64 add2(u64 a, u64 b) {
    u64 d; asm("add.rn.f32x2 %0, %1, %2;" : "=l"(d) : "l"(a), "l"(b)); return d;
}
__device__ __forceinline__ u64 mul2(u64 a, u64 b) {
    u64 d; asm("mul.rn.f32x2 %0, %1, %2;" : "=l"(d) : "l"(a), "l"(b)); return d;
}
__device__ __forceinline__ u64 bc2(float v) {
    u64 r; asm("mov.b64 %0, {%1, %1};" : "=l"(r) : "f"(v)); return r;
}

// Packed fast 2^t on FMA+ALU pipes (no MUFU). Magic-number split + deg-4 poly.
// rel err ~4e-5, valid |t| < 126.
__device__ __forceinline__ u64 ex2fast2(u64 t) {
    const u64 y  = add2(t, bc2(12582912.0f));
    const u64 ii = add2(y, bc2(-12582912.0f));
    const u64 f  = fma2(bc2(-1.0f), ii, t);
    const u64 p  = fma2(fma2(fma2(fma2(bc2(0.0096181291f), f, bc2(0.0555041087f)),
                       f, bc2(0.2402265069f)), f, bc2(0.6931471806f)), f, bc2(1.0f));
    float ylo, yhi;
    upk(y, ylo, yhi);
    const unsigned slo = (__float_as_uint(ylo) << 23) + 0x3F800000u;
    const unsigned shi = (__float_as_uint(yhi) << 23) + 0x3F800000u;
    return mul2(p, pk(__uint_as_float(slo), __uint_as_float(shi)));
}

struct NckC { u64 cA2, dA2, cB2, dB2, cG2; };

// packed nck: e1,e2 on MUFU, e3 on FMA pipe, 1 rcp/element (6 MUFU per call)
__device__ __forceinline__ u64 nck2p(u64 zz, const NckC& C) {
    const u64 t1 = fma2(bc2(-L2E / 8.98f), zz, bc2(6.39f * L2E));
    const u64 t2 = fma2(bc2(-L2E / 4.25f), zz, bc2(-4.4f * L2E));
    const u64 t3 = fma2(bc2(-0.132f * L2E), zz, bc2(0.132f * 16.74f * L2E));
    float x1a, x1b, x2a, x2b;
    upk(t1, x1a, x1b); upk(t2, x2a, x2b);
    const u64 e1 = pk(ex2f(x1a), ex2f(x1b));
    const u64 e2 = pk(ex2f(x2a), ex2f(x2b));
    const u64 e3 = ex2fast2(t3);
    const u64 a1 = add2(e1, bc2(1.0f));
    const u64 a2 = add2(e2, bc2(1.0f));
    const u64 a3 = add2(e3, bc2(0.436f));
    const u64 d12 = mul2(a1, a2);
    const u64 den = mul2(d12, a3);
    float dla, dlb;
    upk(den, dla, dlb);
    const u64 R = pk(rcpf(dla), rcpf(dlb));
    const u64 n1 = fma2(C.cA2, zz, C.dA2);
    const u64 n2 = fma2(C.cB2, zz, C.dB2);
    const u64 q = fma2(n1, a2, mul2(n2, a1));
    const u64 num = fma2(q, a3, mul2(C.cG2, d12));
    return mul2(num, R);
}

// shuffle both halves of a packed pair to the same source lane, gathering
// the two children (2N-1-2k, 2N-2-2k) for tail levels.
__device__ __forceinline__ void tail_gather(float lo, float hi, int ia,
                                            u64& pa, u64& pb) {
    pa = pk(__shfl_sync(FULL, lo, ia), __shfl_sync(FULL, hi, ia));
    pb = pk(__shfl_sync(FULL, lo, ia - 1), __shfl_sync(FULL, hi, ia - 1));
}

// 2 elements per warp, fully packed f32x2 (tree levels AND tail).
__global__ __launch_bounds__(256) void asym_tree_kernel(
    const float* __restrict__ x, TreeParams P, float* __restrict__ out, int B) {
    __shared__ float sm[SM_TOT];

    const int tid = threadIdx.x;
    const int lane = tid & 31;

    // ---- stage params, lane-fastest transposed layouts ----
    {
        const int t = tid >> 5, l = tid & 31;
        const int r = l * 8 + t;
        sm[L0W + tid] = P.w[0][255 - r];
        sm[L0B + tid] = P.b[0][510 - r];
    }
    if (tid < 128) {
        const int s = tid >> 5, l = tid & 31;
        const int k = l * 4 + s;
        sm[L1Wa + tid] = P.w[1][2 * k];
        sm[L1Wb + tid] = P.w[1][2 * k + 1];
        sm[L1B + tid]  = P.b[1][127 + k];
    }
    if (tid < 64) {
        const int s = tid >> 5, l = tid & 31;
        const int k = l * 2 + s;
        sm[L2Wa + tid] = P.w[2][2 * k];
        sm[L2Wb + tid] = P.w[2][2 * k + 1];
        sm[L2B + tid]  = P.b[2][63 + k];
    }
    if (tid < 32) {
        sm[L3Wa + tid] = P.w[3][2 * tid];
        sm[L3Wb + tid] = P.w[3][2 * tid + 1];
        sm[L3B + tid]  = P.b[3][31 + tid];
        sm[L4W + tid]  = P.w[4][tid];
    }
    if (tid < 16) {
        sm[L4B + tid] = P.b[4][15 + tid];
        sm[L5W + tid] = P.w[5][tid];
    }
    if (tid < 8) {
        sm[L5B + tid] = P.b[5][7 + tid];
        sm[L6W + tid] = P.w[6][tid];
    }
    if (tid < 4) {
        sm[L6B + tid] = P.b[6][3 + tid];
        sm[L7W + tid] = P.w[7][tid];
    }
    if (tid < 2) {
        sm[L7B + tid] = P.b[7][1 + tid];
        sm[L8W + tid] = P.w[8][tid];
    }
    if (tid == 0) {
        sm[L8B] = P.b[8][0];
        sm[SC + 0] = P.alpha[0];  sm[SC + 1] = P.beta[0]; sm[SC + 2] = P.gamma[0];
        sm[SC + 3] = P.root_w[0]; sm[SC + 4] = P.root_b[0];
    }
    __syncthreads();

    const float A = sm[SC], Bt = sm[SC + 1], G = sm[SC + 2];
    NckC C;
    C.cA2 = bc2(A * 0.0878f); C.dA2 = bc2(-A * 0.0878f * 113.68f);
    C.cB2 = bc2(Bt * 0.129f); C.dB2 = bc2(-Bt * 0.129f * 69.62f);
    C.cG2 = bc2(G * 2.23f);

    const int warp = (blockIdx.x * 256 + tid) >> 5;
    const int e0 = warp * 2;
    if (e0 >= B) return;

    const float* xeA = x + (size_t)e0 * 256;
    const float* xeB = xeA + 256;

    // ---- levels 0-3, one packed pair stream (staged x loads) ----
    u64 t1[4];
#pragma unroll
    for (int h = 0; h < 2; ++h) {                  // h: which float4 of x
        const float4 xA = reinterpret_cast<const float4*>(xeA)[lane * 2 + h];
        const float4 xB = reinterpret_cast<const float4*>(xeB)[lane * 2 + h];
        const u64 xp[4] = {pk(xA.x, xB.x), pk(xA.y, xB.y),
                           pk(xA.z, xB.z), pk(xA.w, xB.w)};
#pragma unroll
        for (int q = 0; q < 2; ++q) {              // 2 level-1 outputs per float4
            const int s = h * 2 + q;
            const u64 z0 = fma2(bc2(sm[L0W + (2 * s) * 32 + lane]), xp[2 * q],
                                bc2(sm[L0B + (2 * s) * 32 + lane]));
            const u64 z1 = fma2(bc2(sm[L0W + (2 * s + 1) * 32 + lane]), xp[2 * q + 1],
                                bc2(sm[L0B + (2 * s + 1) * 32 + lane]));
            const u64 u0 = nck2p(z0, C);
            const u64 u1 = nck2p(z1, C);
            const u64 zl1 = fma2(bc2(sm[L1Wa + s * 32 + lane]), u0,
                           fma2(bc2(sm[L1Wb + s * 32 + lane]), u1,
                                bc2(sm[L1B + s * 32 + lane])));
            t1[s] = nck2p(zl1, C);
        }
    }

    // reversal: shfl.xor(31) each half + slot flip
    u64 u[4];
#pragma unroll
    for (int s = 0; s < 4; ++s) {
        float lo, hi;
        upk(t1[3 - s], lo, hi);
        u[s] = pk(__shfl_xor_sync(FULL, lo, 31), __shfl_xor_sync(FULL, hi, 31));
    }

    // level 2: N=64, 2 outputs/lane
    u64 t2[2];
#pragma unroll
    for (int s = 0; s < 2; ++s) {
        const u64 z = fma2(bc2(sm[L2Wa + s * 32 + lane]), u[2 * s],
                     fma2(bc2(sm[L2Wb + s * 32 + lane]), u[2 * s + 1],
                          bc2(sm[L2B + s * 32 + lane])));
        t2[s] = nck2p(z, C);
    }
    float lo1, hi1, lo0, hi0;
    upk(t2[1], lo1, hi1);
    upk(t2[0], lo0, hi0);
    const u64 r0 = pk(__shfl_xor_sync(FULL, lo1, 31), __shfl_xor_sync(FULL, hi1, 31));
    const u64 r1 = pk(__shfl_xor_sync(FULL, lo0, 31), __shfl_xor_sync(FULL, hi0, 31));

    // level 3: N=32 -> natural order per lane
    const u64 z3 = fma2(bc2(sm[L3Wa + lane]), r0,
                  fma2(bc2(sm[L3Wb + lane]), r1, bc2(sm[L3B + lane])));
    float clo, chi;
    upk(nck2p(z3, C), clo, chi);

    // ---- tail levels 4-8, packed (both elements in lo/hi halves) ----
    // level l output k lives on lane k; children at lanes 2N-1-2k, 2N-2-2k.
    // level 4: N=16
    {
        const int k = lane & 15;
        u64 pa, pb;
        tail_gather(clo, chi, 31 - 2 * k, pa, pb);
        const u64 z = fma2(bc2(sm[L4W + 2 * k]), pa,
                     fma2(bc2(sm[L4W + 2 * k + 1]), pb, bc2(sm[L4B + k])));
        upk(nck2p(z, C), clo, chi);
    }
    // level 5: N=8
    {
        const int k = lane & 7;
        u64 pa, pb;
        tail_gather(clo, chi, 15 - 2 * k, pa, pb);
        const u64 z = fma2(bc2(sm[L5W + 2 * k]), pa,
                     fma2(bc2(sm[L5W + 2 * k + 1]), pb, bc2(sm[L5B + k])));
        upk(nck2p(z, C), clo, chi);
    }
    // level 6: N=4
    {
        const int k = lane & 3;
        u64 pa, pb;
        tail_gather(clo, chi, 7 - 2 * k, pa, pb);
        const u64 z = fma2(bc2(sm[L6W + 2 * k]), pa,
                     fma2(bc2(sm[L6W + 2 * k + 1]), pb, bc2(sm[L6B + k])));
        upk(nck2p(z, C), clo, chi);
    }
    // level 7: N=2
    {
        const int k = lane & 1;
        u64 pa, pb;
        tail_gather(clo, chi, 3 - 2 * k, pa, pb);
        const u64 z = fma2(bc2(sm[L7W + 2 * k]), pa,
                     fma2(bc2(sm[L7W + 2 * k + 1]), pb, bc2(sm[L7B + k])));
        upk(nck2p(z, C), clo, chi);
    }
    // level 8: N=1 + root sigmoid
    {
        u64 pa, pb;
        tail_gather(clo, chi, 1, pa, pb);
        const u64 z = fma2(bc2(sm[L8W]), pa,
                     fma2(bc2(sm[L8W + 1]), pb, bc2(sm[L8B])));
        const u64 v8 = nck2p(z, C);
        if (lane == 0) {
            float v8lo, v8hi;
            upk(v8, v8lo, v8hi);
            const float t0 = fmaf(v8lo, sm[SC + 3], sm[SC + 4]);
            const float t1r = fmaf(v8hi, sm[SC + 3], sm[SC + 4]);
            out[e0]     = rcpf(1.0f + ex2f(-t0 * L2E));
            out[e0 + 1] = rcpf(1.0f + ex2f(-t1r * L2E));
        }
    }
}

extern "C" void kernel_launch(void* const* d_in, const int* in_sizes, int n_in,
                              void* d_out, int out_size) {
    const float* x = (const float*)d_in[0];
    TreeParams P;
    if (in_sizes[2] == 511) {
        for (int l = 0; l < 9; ++l) {
            P.w[l] = (const float*)d_in[1 + 2 * l];
            P.b[l] = (const float*)d_in[2 + 2 * l];
        }
    } else {
        for (int l = 0; l < 9; ++l) {
            P.w[l] = (const float*)d_in[1 + l];
            P.b[l] = (const float*)d_in[10 + l];
        }
    }
    P.alpha  = (const float*)d_in[19];
    P.beta   = (const float*)d_in[20];
    P.gamma  = (const float*)d_in[21];
    P.root_w = (const float*)d_in[22];
    P.root_b = (const float*)d_in[23];

    const int B = in_sizes[0] / 256;              // 32768
    const int warps = (B + 1) / 2;                // 2 elements per warp -> 16384
    const int grid = (warps + 7) / 8;             // 8 warps per 256-thread block
    asym_tree_kernel<<<grid, 256>>>(x, P, (float*)d_out, B);
}

// round 10
// speedup vs baseline: 1.3401x; 1.3401x over previous
#include <cuda_runtime.h>

#define FULL 0xffffffffu
#define L2E 1.4426950408889634f

typedef unsigned long long u64;

// shared layout offsets (floats), all lane-fastest (conflict-free)
#define L0W 0
#define L0B 256
#define L1Wa 512
#define L1Wb 640
#define L1B 768
#define L2Wa 896
#define L2Wb 960
#define L2B 1024
#define L3Wa 1088
#define L3Wb 1120
#define L3B 1152
#define L4W 1184
#define L4B 1216
#define L5W 1232
#define L5B 1248
#define L6W 1256
#define L6B 1264
#define L7W 1268
#define L7B 1272
#define L8W 1274
#define L8B 1276
#define SC  1280
#define SM_TOT 1288

struct TreeParams {
    const float* w[9];
    const float* b[9];
    const float* alpha;
    const float* beta;
    const float* gamma;
    const float* root_w;
    const float* root_b;
};

__device__ __forceinline__ float tanhap(float x) {
    float y; asm("tanh.approx.f32 %0, %1;" : "=f"(y) : "f"(x)); return y;
}

// ---- f32x2 packed helpers ----
__device__ __forceinline__ u64 pk(float lo, float hi) {
    u64 r; asm("mov.b64 %0, {%1, %2};" : "=l"(r) : "f"(lo), "f"(hi)); return r;
}
__device__ __forceinline__ void upk(u64 v, float& lo, float& hi) {
    asm("mov.b64 {%0, %1}, %2;" : "=f"(lo), "=f"(hi) : "l"(v));
}
__device__ __forceinline__ u64 fma2(u64 a, u64 b, u64 c) {
    u64 d; asm("fma.rn.f32x2 %0, %1, %2, %3;" : "=l"(d) : "l"(a), "l"(b), "l"(c)); return d;
}
__device__ __forceinline__ u64 add2(u64 a, u64 b) {
    u64 d; asm("add.rn.f32x2 %0, %1, %2;" : "=l"(d) : "l"(a), "l"(b)); return d;
}
__device__ __forceinline__ u64 bc2(float v) {
    u64 r; asm("mov.b64 %0, {%1, %1};" : "=l"(r) : "f"(v)); return r;
}

// tanh-form nck:
//   1/(1+e^v) = 0.5 + 0.5*tanh(-v/2)
//   nck(z) = n1/(1+e^{v1}) + n2/(1+e^{v2}) + cG/(0.436+e^{u})
// with 0.436+e^u = 0.436*(1+e^{u-ln0.436}):
//   nck = (m1+m2+mg) + m1*th1 + m2*th2 + mg*th3
//   m1 = 0.5*alpha*0.0878*(z-113.68), m2 = 0.5*beta*0.129*(z-69.62)
//   mg = 0.5*gamma*2.23/0.436
//   th1 = tanh(z/17.96 - 3.195)            (= tanh(-v1/2))
//   th2 = tanh(z/8.5 + 2.2)
//   th3 = tanh(0.066*z - 1.520034)         (ln 0.436 = -0.830068)
// 3 MUFU (tanh) per nck, no rcp/ex2, no denominator chain.
#define TK1 (1.0f / 17.96f)
#define TC1 (-3.195f)
#define TK2 (1.0f / 8.5f)
#define TC2 (2.2f)
#define TK3 (0.066f)
#define TC3 (-1.5200339f)

struct NckC { u64 cA2, dA2, cB2, dB2, mg2; };

// scalar nck (tail levels): 3 tanh
__device__ __forceinline__ float nck_eval(float z, float cA2, float dA2,
                                          float cB2, float dB2, float mg) {
    const float th1 = tanhap(fmaf(TK1, z, TC1));
    const float th2 = tanhap(fmaf(TK2, z, TC2));
    const float th3 = tanhap(fmaf(TK3, z, TC3));
    const float m1 = fmaf(cA2, z, dA2);
    const float m2 = fmaf(cB2, z, dB2);
    const float s = m1 + m2 + mg;
    return fmaf(m1, th1, fmaf(m2, th2, fmaf(mg, th3, s)));
}

// packed nck: 2 elements, 6 tanh (scalar MUFU), everything else f32x2
__device__ __forceinline__ u64 nck2p(u64 zz, const NckC& C) {
    const u64 h1 = fma2(bc2(TK1), zz, bc2(TC1));
    const u64 h2 = fma2(bc2(TK2), zz, bc2(TC2));
    const u64 h3 = fma2(bc2(TK3), zz, bc2(TC3));
    float a1, b1, a2, b2, a3, b3;
    upk(h1, a1, b1); upk(h2, a2, b2); upk(h3, a3, b3);
    const u64 th1 = pk(tanhap(a1), tanhap(b1));
    const u64 th2 = pk(tanhap(a2), tanhap(b2));
    const u64 th3 = pk(tanhap(a3), tanhap(b3));
    const u64 m1 = fma2(C.cA2, zz, C.dA2);
    const u64 m2 = fma2(C.cB2, zz, C.dB2);
    const u64 s = add2(add2(m1, m2), C.mg2);
    u64 r = fma2(C.mg2, th3, s);
    r = fma2(m2, th2, r);
    r = fma2(m1, th1, r);
    return r;
}

// One warp per 4 batch elements (R5 structure, tanh math).
__global__ __launch_bounds__(256) void asym_tree_kernel(
    const float* __restrict__ x, TreeParams P, float* __restrict__ out, int B) {
    __shared__ float sm[SM_TOT];

    const int tid = threadIdx.x;
    const int lane = tid & 31;

    // ---- stage params, lane-fastest transposed layouts ----
    {
        const int t = tid >> 5, l = tid & 31;
        const int r = l * 8 + t;
        sm[L0W + tid] = P.w[0][255 - r];
        sm[L0B + tid] = P.b[0][510 - r];
    }
    if (tid < 128) {
        const int s = tid >> 5, l = tid & 31;
        const int k = l * 4 + s;
        sm[L1Wa + tid] = P.w[1][2 * k];
        sm[L1Wb + tid] = P.w[1][2 * k + 1];
        sm[L1B + tid]  = P.b[1][127 + k];
    }
    if (tid < 64) {
        const int s = tid >> 5, l = tid & 31;
        const int k = l * 2 + s;
        sm[L2Wa + tid] = P.w[2][2 * k];
        sm[L2Wb + tid] = P.w[2][2 * k + 1];
        sm[L2B + tid]  = P.b[2][63 + k];
    }
    if (tid < 32) {
        sm[L3Wa + tid] = P.w[3][2 * tid];
        sm[L3Wb + tid] = P.w[3][2 * tid + 1];
        sm[L3B + tid]  = P.b[3][31 + tid];
        sm[L4W + tid]  = P.w[4][tid];
    }
    if (tid < 16) {
        sm[L4B + tid] = P.b[4][15 + tid];
        sm[L5W + tid] = P.w[5][tid];
    }
    if (tid < 8) {
        sm[L5B + tid] = P.b[5][7 + tid];
        sm[L6W + tid] = P.w[6][tid];
    }
    if (tid < 4) {
        sm[L6B + tid] = P.b[6][3 + tid];
        sm[L7W + tid] = P.w[7][tid];
    }
    if (tid < 2) {
        sm[L7B + tid] = P.b[7][1 + tid];
        sm[L8W + tid] = P.w[8][tid];
    }
    if (tid == 0) {
        sm[L8B] = P.b[8][0];
        sm[SC + 0] = P.alpha[0];  sm[SC + 1] = P.beta[0]; sm[SC + 2] = P.gamma[0];
        sm[SC + 3] = P.root_w[0]; sm[SC + 4] = P.root_b[0];
    }
    __syncthreads();

    const float A = sm[SC], Bt = sm[SC + 1], G = sm[SC + 2];
    const float cA2s = A * 0.0439f,  dA2s = -A * 0.0439f * 113.68f;
    const float cB2s = Bt * 0.0645f, dB2s = -Bt * 0.0645f * 69.62f;
    const float mgs = G * 0.5f * (2.23f / 0.436f);
    NckC C;
    C.cA2 = bc2(cA2s); C.dA2 = bc2(dA2s);
    C.cB2 = bc2(cB2s); C.dB2 = bc2(dB2s);
    C.mg2 = bc2(mgs);

    const int warp = (blockIdx.x * 256 + tid) >> 5;
    const int e0 = warp * 4;
    if (e0 >= B) return;

    // ---- levels 0-3, two elements packed per f32x2 stream, two pairs ----
    float c[4];
#pragma unroll
    for (int p = 0; p < 2; ++p) {
        const int eA = e0 + 2 * p;
        const float* xeA = x + (size_t)eA * 256;
        const float* xeB = xeA + 256;
        const float4 a4A = reinterpret_cast<const float4*>(xeA)[lane * 2];
        const float4 b4A = reinterpret_cast<const float4*>(xeA)[lane * 2 + 1];
        const float4 a4B = reinterpret_cast<const float4*>(xeB)[lane * 2];
        const float4 b4B = reinterpret_cast<const float4*>(xeB)[lane * 2 + 1];
        const float xvA[8] = {a4A.x, a4A.y, a4A.z, a4A.w, b4A.x, b4A.y, b4A.z, b4A.w};
        const float xvB[8] = {a4B.x, a4B.y, a4B.z, a4B.w, b4B.x, b4B.y, b4B.z, b4B.w};

        // levels 0+1 fused, packed
        u64 t1[4];
#pragma unroll
        for (int s = 0; s < 4; ++s) {
            const u64 z0 = fma2(bc2(sm[L0W + (2 * s) * 32 + lane]),
                                pk(xvA[2 * s], xvB[2 * s]),
                                bc2(sm[L0B + (2 * s) * 32 + lane]));
            const u64 z1 = fma2(bc2(sm[L0W + (2 * s + 1) * 32 + lane]),
                                pk(xvA[2 * s + 1], xvB[2 * s + 1]),
                                bc2(sm[L0B + (2 * s + 1) * 32 + lane]));
            const u64 u0 = nck2p(z0, C);
            const u64 u1 = nck2p(z1, C);
            const u64 zl1 = fma2(bc2(sm[L1Wa + s * 32 + lane]), u0,
                           fma2(bc2(sm[L1Wb + s * 32 + lane]), u1,
                                bc2(sm[L1B + s * 32 + lane])));
            t1[s] = nck2p(zl1, C);
        }

        // reversal: unpack, shfl.xor(31) each half, repack (slot flip)
        u64 u[4];
#pragma unroll
        for (int s = 0; s < 4; ++s) {
            float lo, hi;
            upk(t1[3 - s], lo, hi);
            u[s] = pk(__shfl_xor_sync(FULL, lo, 31), __shfl_xor_sync(FULL, hi, 31));
        }

        // level 2: N=64, 2 outputs/lane, packed
        u64 t2[2];
#pragma unroll
        for (int s = 0; s < 2; ++s) {
            const u64 z = fma2(bc2(sm[L2Wa + s * 32 + lane]), u[2 * s],
                         fma2(bc2(sm[L2Wb + s * 32 + lane]), u[2 * s + 1],
                              bc2(sm[L2B + s * 32 + lane])));
            t2[s] = nck2p(z, C);
        }
        float lo1, hi1, lo0, hi0;
        upk(t2[1], lo1, hi1);
        upk(t2[0], lo0, hi0);
        const u64 r0 = pk(__shfl_xor_sync(FULL, lo1, 31), __shfl_xor_sync(FULL, hi1, 31));
        const u64 r1 = pk(__shfl_xor_sync(FULL, lo0, 31), __shfl_xor_sync(FULL, hi0, 31));

        // level 3: N=32, 1 output/lane, packed -> natural order
        const u64 z3 = fma2(bc2(sm[L3Wa + lane]), r0,
                      fma2(bc2(sm[L3Wb + lane]), r1, bc2(sm[L3B + lane])));
        const u64 cc = nck2p(z3, C);
        upk(cc, c[2 * p], c[2 * p + 1]);
    }

    // ---- level 4: N=16, 2 elements per warp-nck (scalar tail) ----
    const bool hi = lane >= 16;
    const int k4 = lane & 15;
    const int i4a = 31 - 2 * k4;
    const int i4b = 30 - 2 * k4;
    const float w4a = sm[L4W + 2 * k4], w4b = sm[L4W + 2 * k4 + 1];
    const float bb4 = sm[L4B + k4];

    float v4p0, v4p1;
    {
        const float a0 = __shfl_sync(FULL, c[0], i4a);
        const float a1 = __shfl_sync(FULL, c[1], i4a);
        const float b0 = __shfl_sync(FULL, c[0], i4b);
        const float b1 = __shfl_sync(FULL, c[1], i4b);
        const float pa = hi ? a1 : a0;
        const float pb = hi ? b1 : b0;
        v4p0 = nck_eval(fmaf(w4a, pa, fmaf(w4b, pb, bb4)), cA2s, dA2s, cB2s, dB2s, mgs);
    }
    {
        const float a0 = __shfl_sync(FULL, c[2], i4a);
        const float a1 = __shfl_sync(FULL, c[3], i4a);
        const float b0 = __shfl_sync(FULL, c[2], i4b);
        const float b1 = __shfl_sync(FULL, c[3], i4b);
        const float pa = hi ? a1 : a0;
        const float pb = hi ? b1 : b0;
        v4p1 = nck_eval(fmaf(w4a, pa, fmaf(w4b, pb, bb4)), cA2s, dA2s, cB2s, dB2s, mgs);
    }

    // ---- level 5: N=8, all 4 elements in one warp-nck ----
    float v5;
    {
        const int k5 = lane & 7;
        const int half = (lane >> 3) & 1;
        const int s5a = half * 16 + (15 - 2 * k5);
        const int s5b = s5a - 1;
        const float w5a = sm[L5W + 2 * k5], w5b = sm[L5W + 2 * k5 + 1];
        const float bb5 = sm[L5B + k5];
        const float A0 = __shfl_sync(FULL, v4p0, s5a);
        const float A1 = __shfl_sync(FULL, v4p1, s5a);
        const float B0 = __shfl_sync(FULL, v4p0, s5b);
        const float B1 = __shfl_sync(FULL, v4p1, s5b);
        const float pa = hi ? A1 : A0;
        const float pb = hi ? B1 : B0;
        v5 = nck_eval(fmaf(w5a, pa, fmaf(w5b, pb, bb5)), cA2s, dA2s, cB2s, dB2s, mgs);
    }

    // ---- level 6: N=4 (lane = 4e + k) ----
    float v6;
    {
        const int k6 = lane & 3;
        const int e6 = lane >> 2;
        const int s6 = (8 * e6 + 7 - 2 * k6) & 31;
        const float w6a = sm[L6W + 2 * k6], w6b = sm[L6W + 2 * k6 + 1];
        const float bb6 = sm[L6B + k6];
        const float pa = __shfl_sync(FULL, v5, s6);
        const float pb = __shfl_sync(FULL, v5, (s6 - 1) & 31);
        v6 = nck_eval(fmaf(w6a, pa, fmaf(w6b, pb, bb6)), cA2s, dA2s, cB2s, dB2s, mgs);
    }

    // ---- level 7: N=2 (lane = 2e + k) ----
    float v7;
    {
        const int k7 = lane & 1;
        const int e7 = (lane >> 1) & 7;
        const int s7 = (4 * e7 + 3 - 2 * k7) & 31;
        const float w7a = sm[L7W + 2 * k7], w7b = sm[L7W + 2 * k7 + 1];
        const float bb7 = sm[L7B + k7];
        const float pa = __shfl_sync(FULL, v6, s7);
        const float pb = __shfl_sync(FULL, v6, (s7 - 1) & 31);
        v7 = nck_eval(fmaf(w7a, pa, fmaf(w7b, pb, bb7)), cA2s, dA2s, cB2s, dB2s, mgs);
    }

    // ---- level 8: N=1 (lane = e) + root sigmoid via tanh ----
    {
        const int e8 = lane & 3;
        const float pa = __shfl_sync(FULL, v7, (2 * e8 + 1) & 31);
        const float pb = __shfl_sync(FULL, v7, (2 * e8) & 31);
        const float v8 = nck_eval(fmaf(sm[L8W], pa, fmaf(sm[L8W + 1], pb, sm[L8B])),
                                  cA2s, dA2s, cB2s, dB2s, mgs);
        if (lane < 4 && e0 + lane < B) {
            const float t = fmaf(v8, sm[SC + 3], sm[SC + 4]);
            // sigmoid(t) = 0.5 + 0.5*tanh(t/2)
            out[e0 + lane] = fmaf(0.5f, tanhap(0.5f * t), 0.5f);
        }
    }
}

extern "C" void kernel_launch(void* const* d_in, const int* in_sizes, int n_in,
                              void* d_out, int out_size) {
    const float* x = (const float*)d_in[0];
    TreeParams P;
    if (in_sizes[2] == 511) {
        for (int l = 0; l < 9; ++l) {
            P.w[l] = (const float*)d_in[1 + 2 * l];
            P.b[l] = (const float*)d_in[2 + 2 * l];
        }
    } else {
        for (int l = 0; l < 9; ++l) {
            P.w[l] = (const float*)d_in[1 + l];
            P.b[l] = (const float*)d_in[10 + l];
        }
    }
    P.alpha  = (const float*)d_in[19];
    P.beta   = (const float*)d_in[20];
    P.gamma  = (const float*)d_in[21];
    P.root_w = (const float*)d_in[22];
    P.root_b = (const float*)d_in[23];

    const int B = in_sizes[0] / 256;              // 32768
    const int warps = (B + 3) / 4;                // 4 elements per warp
    const int grid = (warps + 7) / 8;             // 8 warps per 256-thread block
    asym_tree_kernel<<<grid, 256>>>(x, P, (float*)d_out, B);
}

// round 12
// speedup vs baseline: 1.3679x; 1.0207x over previous
#include <cuda_runtime.h>

#define FULL 0xffffffffu
#define L2E 1.4426950408889634f

typedef unsigned long long u64;

// shared layout offsets (floats), all lane-fastest (conflict-free)
#define L0W 0
#define L0B 256
#define L1Wa 512
#define L1Wb 640
#define L1B 768
#define L2Wa 896
#define L2Wb 960
#define L2B 1024
#define L3Wa 1088
#define L3Wb 1120
#define L3B 1152
#define L4W 1184
#define L4B 1216
#define L5W 1232
#define L5B 1248
#define L6W 1256
#define L6B 1264
#define L7W 1268
#define L7B 1272
#define L8W 1274
#define L8B 1276
#define SC  1280
#define SM_TOT 1288

struct TreeParams {
    const float* w[9];
    const float* b[9];
    const float* alpha;
    const float* beta;
    const float* gamma;
    const float* root_w;
    const float* root_b;
};

__device__ __forceinline__ float tanhap(float x) {
    float y; asm("tanh.approx.f32 %0, %1;" : "=f"(y) : "f"(x)); return y;
}

// ---- f32x2 packed helpers ----
__device__ __forceinline__ u64 pk(float lo, float hi) {
    u64 r; asm("mov.b64 %0, {%1, %2};" : "=l"(r) : "f"(lo), "f"(hi)); return r;
}
__device__ __forceinline__ void upk(u64 v, float& lo, float& hi) {
    asm("mov.b64 {%0, %1}, %2;" : "=f"(lo), "=f"(hi) : "l"(v));
}
__device__ __forceinline__ u64 fma2(u64 a, u64 b, u64 c) {
    u64 d; asm("fma.rn.f32x2 %0, %1, %2, %3;" : "=l"(d) : "l"(a), "l"(b), "l"(c)); return d;
}
__device__ __forceinline__ u64 add2(u64 a, u64 b) {
    u64 d; asm("add.rn.f32x2 %0, %1, %2;" : "=l"(d) : "l"(a), "l"(b)); return d;
}
__device__ __forceinline__ u64 bc2(float v) {
    u64 r; asm("mov.b64 %0, {%1, %1};" : "=l"(r) : "f"(v)); return r;
}

// tanh-form nck:
//   nck = (m1+m2+mg) + m1*th1 + m2*th2 + mg*th3
//   m1 = 0.5*alpha*0.0878*(z-113.68), m2 = 0.5*beta*0.129*(z-69.62)
//   mg = 0.5*gamma*2.23/0.436
//   th1 = tanh(z/17.96 - 3.195), th2 = tanh(z/8.5 + 2.2),
//   th3 = tanh(0.066*z - 1.5200339)
// 3 MUFU (tanh) per nck, no rcp/ex2, no denominator chain.
#define TK1 (1.0f / 17.96f)
#define TC1 (-3.195f)
#define TK2 (1.0f / 8.5f)
#define TC2 (2.2f)
#define TK3 (0.066f)
#define TC3 (-1.5200339f)

struct NckC { u64 cA2, dA2, cB2, dB2, mg2; };

// scalar nck (tail levels): 3 tanh
__device__ __forceinline__ float nck_eval(float z, float cA2, float dA2,
                                          float cB2, float dB2, float mg) {
    const float th1 = tanhap(fmaf(TK1, z, TC1));
    const float th2 = tanhap(fmaf(TK2, z, TC2));
    const float th3 = tanhap(fmaf(TK3, z, TC3));
    const float m1 = fmaf(cA2, z, dA2);
    const float m2 = fmaf(cB2, z, dB2);
    const float s = m1 + m2 + mg;
    return fmaf(m1, th1, fmaf(m2, th2, fmaf(mg, th3, s)));
}

// packed nck: 2 independent evaluations, 6 tanh, everything else f32x2
__device__ __forceinline__ u64 nck2p(u64 zz, const NckC& C) {
    const u64 h1 = fma2(bc2(TK1), zz, bc2(TC1));
    const u64 h2 = fma2(bc2(TK2), zz, bc2(TC2));
    const u64 h3 = fma2(bc2(TK3), zz, bc2(TC3));
    float a1, b1, a2, b2, a3, b3;
    upk(h1, a1, b1); upk(h2, a2, b2); upk(h3, a3, b3);
    const u64 th1 = pk(tanhap(a1), tanhap(b1));
    const u64 th2 = pk(tanhap(a2), tanhap(b2));
    const u64 th3 = pk(tanhap(a3), tanhap(b3));
    const u64 m1 = fma2(C.cA2, zz, C.dA2);
    const u64 m2 = fma2(C.cB2, zz, C.dB2);
    const u64 s = add2(add2(m1, m2), C.mg2);
    u64 r = fma2(C.mg2, th3, s);
    r = fma2(m2, th2, r);
    r = fma2(m1, th1, r);
    return r;
}

// One warp per 4 batch elements; 128-thread blocks -> 7 blocks/SM (28 warps).
__global__ __launch_bounds__(128) void asym_tree_kernel(
    const float* __restrict__ x, TreeParams P, float* __restrict__ out, int B) {
    __shared__ float sm[SM_TOT];

    const int tid = threadIdx.x;
    const int lane = tid & 31;

    // ---- stage params, lane-fastest transposed layouts (128 threads) ----
    for (int i = tid; i < 256; i += 128) {
        const int t = i >> 5, l = i & 31;
        const int r = l * 8 + t;
        sm[L0W + i] = P.w[0][255 - r];
        sm[L0B + i] = P.b[0][510 - r];
    }
    {
        const int s = tid >> 5, l = tid & 31;
        const int k = l * 4 + s;
        sm[L1Wa + tid] = P.w[1][2 * k];
        sm[L1Wb + tid] = P.w[1][2 * k + 1];
        sm[L1B + tid]  = P.b[1][127 + k];
    }
    if (tid < 64) {
        const int s = tid >> 5, l = tid & 31;
        const int k = l * 2 + s;
        sm[L2Wa + tid] = P.w[2][2 * k];
        sm[L2Wb + tid] = P.w[2][2 * k + 1];
        sm[L2B + tid]  = P.b[2][63 + k];
    }
    if (tid < 32) {
        sm[L3Wa + tid] = P.w[3][2 * tid];
        sm[L3Wb + tid] = P.w[3][2 * tid + 1];
        sm[L3B + tid]  = P.b[3][31 + tid];
        sm[L4W + tid]  = P.w[4][tid];
    }
    if (tid < 16) {
        sm[L4B + tid] = P.b[4][15 + tid];
        sm[L5W + tid] = P.w[5][tid];
    }
    if (tid < 8) {
        sm[L5B + tid] = P.b[5][7 + tid];
        sm[L6W + tid] = P.w[6][tid];
    }
    if (tid < 4) {
        sm[L6B + tid] = P.b[6][3 + tid];
        sm[L7W + tid] = P.w[7][tid];
    }
    if (tid < 2) {
        sm[L7B + tid] = P.b[7][1 + tid];
        sm[L8W + tid] = P.w[8][tid];
    }
    if (tid == 0) {
        sm[L8B] = P.b[8][0];
        sm[SC + 0] = P.alpha[0];  sm[SC + 1] = P.beta[0]; sm[SC + 2] = P.gamma[0];
        sm[SC + 3] = P.root_w[0]; sm[SC + 4] = P.root_b[0];
    }
    __syncthreads();

    const float A = sm[SC], Bt = sm[SC + 1], G = sm[SC + 2];
    const float cA2s = A * 0.0439f,  dA2s = -A * 0.0439f * 113.68f;
    const float cB2s = Bt * 0.0645f, dB2s = -Bt * 0.0645f * 69.62f;
    const float mgs = G * 0.5f * (2.23f / 0.436f);
    NckC C;
    C.cA2 = bc2(cA2s); C.dA2 = bc2(dA2s);
    C.cB2 = bc2(cB2s); C.dB2 = bc2(dB2s);
    C.mg2 = bc2(mgs);

    const int warp = (blockIdx.x * 128 + tid) >> 5;
    const int e0 = warp * 4;
    if (e0 >= B) return;

    // ---- levels 0-3, two elements packed per f32x2 stream, two pairs ----
    float c[4];
#pragma unroll
    for (int p = 0; p < 2; ++p) {
        const int eA = e0 + 2 * p;
        const float* xeA = x + (size_t)eA * 256;
        const float* xeB = xeA + 256;
        const float4 a4A = reinterpret_cast<const float4*>(xeA)[lane * 2];
        const float4 b4A = reinterpret_cast<const float4*>(xeA)[lane * 2 + 1];
        const float4 a4B = reinterpret_cast<const float4*>(xeB)[lane * 2];
        const float4 b4B = reinterpret_cast<const float4*>(xeB)[lane * 2 + 1];
        const float xvA[8] = {a4A.x, a4A.y, a4A.z, a4A.w, b4A.x, b4A.y, b4A.z, b4A.w};
        const float xvB[8] = {a4B.x, a4B.y, a4B.z, a4B.w, b4B.x, b4B.y, b4B.z, b4B.w};

        // levels 0+1 fused, packed
        u64 t1[4];
#pragma unroll
        for (int s = 0; s < 4; ++s) {
            const u64 z0 = fma2(bc2(sm[L0W + (2 * s) * 32 + lane]),
                                pk(xvA[2 * s], xvB[2 * s]),
                                bc2(sm[L0B + (2 * s) * 32 + lane]));
            const u64 z1 = fma2(bc2(sm[L0W + (2 * s + 1) * 32 + lane]),
                                pk(xvA[2 * s + 1], xvB[2 * s + 1]),
                                bc2(sm[L0B + (2 * s + 1) * 32 + lane]));
            const u64 u0 = nck2p(z0, C);
            const u64 u1 = nck2p(z1, C);
            const u64 zl1 = fma2(bc2(sm[L1Wa + s * 32 + lane]), u0,
                           fma2(bc2(sm[L1Wb + s * 32 + lane]), u1,
                                bc2(sm[L1B + s * 32 + lane])));
            t1[s] = nck2p(zl1, C);
        }

        // reversal: unpack, shfl.xor(31) each half, repack (slot flip)
        u64 u[4];
#pragma unroll
        for (int s = 0; s < 4; ++s) {
            float lo, hi;
            upk(t1[3 - s], lo, hi);
            u[s] = pk(__shfl_xor_sync(FULL, lo, 31), __shfl_xor_sync(FULL, hi, 31));
        }

        // level 2: N=64, 2 outputs/lane, packed
        u64 t2[2];
#pragma unroll
        for (int s = 0; s < 2; ++s) {
            const u64 z = fma2(bc2(sm[L2Wa + s * 32 + lane]), u[2 * s],
                         fma2(bc2(sm[L2Wb + s * 32 + lane]), u[2 * s + 1],
                              bc2(sm[L2B + s * 32 + lane])));
            t2[s] = nck2p(z, C);
        }
        float lo1, hi1, lo0, hi0;
        upk(t2[1], lo1, hi1);
        upk(t2[0], lo0, hi0);
        const u64 r0 = pk(__shfl_xor_sync(FULL, lo1, 31), __shfl_xor_sync(FULL, hi1, 31));
        const u64 r1 = pk(__shfl_xor_sync(FULL, lo0, 31), __shfl_xor_sync(FULL, hi0, 31));

        // level 3: N=32, 1 output/lane, packed -> natural order
        const u64 z3 = fma2(bc2(sm[L3Wa + lane]), r0,
                      fma2(bc2(sm[L3Wb + lane]), r1, bc2(sm[L3B + lane])));
        const u64 cc = nck2p(z3, C);
        upk(cc, c[2 * p], c[2 * p + 1]);
    }

    // ---- level 4: N=16, ONE packed call (lo = elems 0/1, hi = elems 2/3) ----
    const bool hi = lane >= 16;
    const int k4 = lane & 15;
    const int i4a = 31 - 2 * k4;
    const int i4b = 30 - 2 * k4;

    float v4p0, v4p1;
    {
        const float a0 = __shfl_sync(FULL, c[0], i4a);
        const float a1 = __shfl_sync(FULL, c[1], i4a);
        const float b0 = __shfl_sync(FULL, c[0], i4b);
        const float b1 = __shfl_sync(FULL, c[1], i4b);
        const float a2 = __shfl_sync(FULL, c[2], i4a);
        const float a3 = __shfl_sync(FULL, c[3], i4a);
        const float b2 = __shfl_sync(FULL, c[2], i4b);
        const float b3 = __shfl_sync(FULL, c[3], i4b);
        const u64 pa = pk(hi ? a1 : a0, hi ? a3 : a2);
        const u64 pb = pk(hi ? b1 : b0, hi ? b3 : b2);
        const u64 z = fma2(bc2(sm[L4W + 2 * k4]), pa,
                     fma2(bc2(sm[L4W + 2 * k4 + 1]), pb, bc2(sm[L4B + k4])));
        upk(nck2p(z, C), v4p0, v4p1);
    }

    // ---- level 5: N=8, all 4 elements in one scalar warp-nck ----
    float v5;
    {
        const int k5 = lane & 7;
        const int half = (lane >> 3) & 1;
        const int s5a = half * 16 + (15 - 2 * k5);
        const int s5b = s5a - 1;
        const float w5a = sm[L5W + 2 * k5], w5b = sm[L5W + 2 * k5 + 1];
        const float bb5 = sm[L5B + k5];
        const float A0 = __shfl_sync(FULL, v4p0, s5a);
        const float A1 = __shfl_sync(FULL, v4p1, s5a);
        const float B0 = __shfl_sync(FULL, v4p0, s5b);
        const float B1 = __shfl_sync(FULL, v4p1, s5b);
        const float pa = hi ? A1 : A0;
        const float pb = hi ? B1 : B0;
        v5 = nck_eval(fmaf(w5a, pa, fmaf(w5b, pb, bb5)), cA2s, dA2s, cB2s, dB2s, mgs);
    }

    // ---- level 6: N=4 (lane = 4e + k) ----
    float v6;
    {
        const int k6 = lane & 3;
        const int e6 = lane >> 2;
        const int s6 = (8 * e6 + 7 - 2 * k6) & 31;
        const float w6a = sm[L6W + 2 * k6], w6b = sm[L6W + 2 * k6 + 1];
        const float bb6 = sm[L6B + k6];
        const float pa = __shfl_sync(FULL, v5, s6);
        const float pb = __shfl_sync(FULL, v5, (s6 - 1) & 31);
        v6 = nck_eval(fmaf(w6a, pa, fmaf(w6b, pb, bb6)), cA2s, dA2s, cB2s, dB2s, mgs);
    }

    // ---- level 7: N=2 (lane = 2e + k) ----
    float v7;
    {
        const int k7 = lane & 1;
        const int e7 = (lane >> 1) & 7;
        const int s7 = (4 * e7 + 3 - 2 * k7) & 31;
        const float w7a = sm[L7W + 2 * k7], w7b = sm[L7W + 2 * k7 + 1];
        const float bb7 = sm[L7B + k7];
        const float pa = __shfl_sync(FULL, v6, s7);
        const float pb = __shfl_sync(FULL, v6, (s7 - 1) & 31);
        v7 = nck_eval(fmaf(w7a, pa, fmaf(w7b, pb, bb7)), cA2s, dA2s, cB2s, dB2s, mgs);
    }

    // ---- level 8: N=1 (lane = e) + root sigmoid via tanh ----
    {
        const int e8 = lane & 3;
        const float pa = __shfl_sync(FULL, v7, (2 * e8 + 1) & 31);
        const float pb = __shfl_sync(FULL, v7, (2 * e8) & 31);
        const float v8 = nck_eval(fmaf(sm[L8W], pa, fmaf(sm[L8W + 1], pb, sm[L8B])),
                                  cA2s, dA2s, cB2s, dB2s, mgs);
        if (lane < 4 && e0 + lane < B) {
            const float t = fmaf(v8, sm[SC + 3], sm[SC + 4]);
            out[e0 + lane] = fmaf(0.5f, tanhap(0.5f * t), 0.5f);
        }
    }
}

extern "C" void kernel_launch(void* const* d_in, const int* in_sizes, int n_in,
                              void* d_out, int out_size) {
    const float* x = (const float*)d_in[0];
    TreeParams P;
    if (in_sizes[2] == 511) {
        for (int l = 0; l < 9; ++l) {
            P.w[l] = (const float*)d_in[1 + 2 * l];
            P.b[l] = (const float*)d_in[2 + 2 * l];
        }
    } else {
        for (int l = 0; l < 9; ++l) {
            P.w[l] = (const float*)d_in[1 + l];
            P.b[l] = (const float*)d_in[10 + l];
        }
    }
    P.alpha  = (const float*)d_in[19];
    P.beta   = (const float*)d_in[20];
    P.gamma  = (const float*)d_in[21];
    P.root_w = (const float*)d_in[22];
    P.root_b = (const float*)d_in[23];

    const int B = in_sizes[0] / 256;              // 32768
    const int warps = (B + 3) / 4;                // 4 elements per warp -> 8192
    const int grid = (warps + 3) / 4;             // 4 warps per 128-thread block
    asym_tree_kernel<<<grid, 128>>>(x, P, (float*)d_out, B);
}